// round 6
// baseline (speedup 1.0000x reference)
#include <cuda_runtime.h>
#include <cstdint>

#define NN   1000
#define FF   64
#define BB   16
#define TT   12
#define CC   10
#define EE   16000
#define SS   (BB*TT)          // 192 snapshots
#define MM   (SS*NN)          // 192000 rows
#define KDIM 576              // 9 * 64
#define FLAT (TT*NN*FF)       // 768000 per batch

// ------------------------- device scratch (static, allowed) -------------------------
__device__ int   g_deg_out[NN];
__device__ int   g_deg_in[NN];
__device__ int   g_ptr_out[NN + 1];
__device__ int   g_ptr_in[NN + 1];
__device__ int   g_cur_out[NN];
__device__ int   g_cur_in[NN];
__device__ int   g_nbr_out[EE];
__device__ float g_val_out[EE];
__device__ int   g_nbr_in[EE];
__device__ float g_invdeg_in[NN];
__device__ float g_Wc[KDIM * 128];            // 576 x 128 combined weights
__device__ float g_basis[(size_t)MM * KDIM];  // 442 MB Chebyshev basis
__device__ float g_hln[(size_t)MM * FF];      // 49 MB post-LN hidden

// ------------------------------- helpers -------------------------------
__device__ __forceinline__ unsigned long long ffma2(unsigned long long a,
                                                    unsigned long long b,
                                                    unsigned long long c) {
    unsigned long long d;
    asm("fma.rn.f32x2 %0, %1, %2, %3;" : "=l"(d) : "l"(a), "l"(b), "l"(c));
    return d;
}

// ------------------------------- setup kernels -------------------------------
__global__ void k_init() {
    int i = blockIdx.x * blockDim.x + threadIdx.x;
    if (i < NN) { g_deg_out[i] = 0; g_deg_in[i] = 0; }
}

__global__ void k_deg(const int* __restrict__ ei) {
    int e = blockIdx.x * blockDim.x + threadIdx.x;
    if (e < EE) {
        atomicAdd(&g_deg_out[ei[e]], 1);       // row = src
        atomicAdd(&g_deg_in[ei[EE + e]], 1);   // col = dst
    }
}

__global__ void k_scan() {
    __shared__ int buf[1024];
    int t = threadIdx.x;
    int v = (t < NN) ? g_deg_in[t] : 0;
    buf[t] = v; __syncthreads();
    for (int off = 1; off < 1024; off <<= 1) {
        int a = buf[t];
        int b = (t >= off) ? buf[t - off] : 0;
        __syncthreads();
        buf[t] = a + b;
        __syncthreads();
    }
    if (t < NN) {
        int incl = buf[t];
        g_ptr_out[t] = incl - v;
        g_cur_out[t] = incl - v;
        g_invdeg_in[t] = (v > 0) ? 1.0f / (float)v : 0.0f;
        if (t == NN - 1) g_ptr_out[NN] = incl;
    }
    __syncthreads();
    int v2 = (t < NN) ? g_deg_out[t] : 0;
    buf[t] = v2; __syncthreads();
    for (int off = 1; off < 1024; off <<= 1) {
        int a = buf[t];
        int b = (t >= off) ? buf[t - off] : 0;
        __syncthreads();
        buf[t] = a + b;
        __syncthreads();
    }
    if (t < NN) {
        int incl = buf[t];
        g_ptr_in[t] = incl - v2;
        g_cur_in[t] = incl - v2;
        if (t == NN - 1) g_ptr_in[NN] = incl;
    }
}

__global__ void k_fill(const int* __restrict__ ei) {
    int e = blockIdx.x * blockDim.x + threadIdx.x;
    if (e < EE) {
        int row = ei[e], col = ei[EE + e];
        int p = atomicAdd(&g_cur_out[col], 1);
        g_nbr_out[p] = row;
        g_val_out[p] = 1.0f / (float)g_deg_out[row];
        int q = atomicAdd(&g_cur_in[row], 1);
        g_nbr_in[q] = col;
    }
}

// Combined weight Wc[j*64+i][c]: c<64 -> z (W_z), c>=64 -> h (W_h)
__global__ void k_wc(const float* __restrict__ Wz, const float* __restrict__ Wh) {
    int idx = blockIdx.x * blockDim.x + threadIdx.x;
    if (idx >= 9 * 64 * 128) return;
    int j = idx / 8192;
    int r = idx - j * 8192;
    int i = r >> 7;
    int c = r & 127;
    const float* W = (c < 64) ? Wz : Wh;
    int f = c & 63;
    float val;
    if (j == 0)       val = W[i * 64 + f] + W[5 * 8192 + i * 64 + f];
    else if (j <= 4)  val = W[(size_t)j * 8192 + i * 64 + f];
    else              val = W[(size_t)(5 + (j - 4)) * 8192 + i * 64 + f];
    g_Wc[(j * 64 + i) * 128 + c] = val;
}

__global__ void k_copyx(const float4* __restrict__ x4) {
    int idx = blockIdx.x * blockDim.x + threadIdx.x;
    if (idx >= MM * 16) return;
    int m = idx >> 4;
    int q = idx & 15;
    float4* dst = (float4*)g_basis;
    dst[(size_t)m * 144 + q] = x4[(size_t)m * 16 + q];
}

// ------------------------------- propagation: L1-resident fgroup split -------------------------------
// CTA = (fgroup of 16 feats, snapshot, direction); 1024 threads = 64 half-warps,
// half-warp per node (strided), lane16 = feature. Per-CTA src working set =
// 1000 nodes x 16 feats x 4B = 64KB -> L1-resident; ~15/16 of gathers hit L1.
__global__ void __launch_bounds__(1024, 2)
k_prop2(int step) {
    int fg  = blockIdx.x;            // 0..3
    int s   = blockIdx.y;            // 0..191
    int dir = blockIdx.z;            // 0 = out, 1 = in
    int tid = threadIdx.x;
    int hw  = tid >> 4;              // 0..63
    int lane16 = tid & 15;

    int srcslot = (step == 1) ? 0 : ((dir ? 4 : 0) + step - 1);
    int dstslot = (dir ? 4 : 0) + step;
    float alpha = (step == 1) ? 1.0f : 2.0f;

    const int* ptr = dir ? g_ptr_in : g_ptr_out;
    const int* nbr = dir ? g_nbr_in : g_nbr_out;
    int foff = fg * 16 + lane16;
    const float* src = g_basis + (size_t)s * NN * KDIM + (size_t)srcslot * 64 + foff;

    for (int n = hw; n < NN; n += 64) {
        int e0 = __ldg(ptr + n), e1 = __ldg(ptr + n + 1);
        float a0 = 0.f, a1 = 0.f;
        int e = e0;
        if (dir) {
            for (; e + 1 < e1; e += 2) {
                int v0 = __ldg(nbr + e);
                int v1 = __ldg(nbr + e + 1);
                a0 += __ldg(src + (size_t)v0 * KDIM);
                a1 += __ldg(src + (size_t)v1 * KDIM);
            }
            if (e < e1) {
                int v0 = __ldg(nbr + e);
                a0 += __ldg(src + (size_t)v0 * KDIM);
            }
            float inv = __ldg(g_invdeg_in + n);
            a0 = (a0 + a1) * inv;
        } else {
            for (; e + 1 < e1; e += 2) {
                int v0 = __ldg(nbr + e);
                int v1 = __ldg(nbr + e + 1);
                float w0 = __ldg(g_val_out + e);
                float w1 = __ldg(g_val_out + e + 1);
                a0 += w0 * __ldg(src + (size_t)v0 * KDIM);
                a1 += w1 * __ldg(src + (size_t)v1 * KDIM);
            }
            if (e < e1) {
                int v0 = __ldg(nbr + e);
                float w0 = __ldg(g_val_out + e);
                a0 += w0 * __ldg(src + (size_t)v0 * KDIM);
            }
            a0 += a1;
        }

        size_t orow = (size_t)(s * NN + n) * KDIM;
        float res = alpha * a0;
        if (step >= 2)
            res -= g_basis[orow + (size_t)(step - 2) * 64 + foff];
        g_basis[orow + (size_t)dstslot * 64 + foff] = res;
    }
}

// ------------------------------- fused GEMM + gate + LN (R1, proven) -------------------------------
__global__ void __launch_bounds__(256, 2)
k_gemm(const float* __restrict__ bz, const float* __restrict__ bh,
       const float* __restrict__ lng, const float* __restrict__ lnb) {
    __shared__ float As[16][128];     // A tile transposed: As[k][m]
    __shared__ float Bsd[16][256];    // B tile, dup-packed {b,b}

    int tid = threadIdx.x;
    int m0  = blockIdx.x * 128;
    int tm  = tid >> 4;
    int tn  = tid & 15;

    unsigned long long acc[4][8];
#pragma unroll
    for (int q = 0; q < 4; q++)
#pragma unroll
        for (int j = 0; j < 8; j++) acc[q][j] = 0ull;

    for (int kt = 0; kt < KDIM; kt += 16) {
#pragma unroll
        for (int l = 0; l < 2; l++) {
            int fi = tid + l * 256;
            int row = fi >> 2, c4 = fi & 3;
            float4 v = *(const float4*)(g_basis + (size_t)(m0 + row) * KDIM + kt + c4 * 4);
            As[c4 * 4 + 0][row] = v.x;
            As[c4 * 4 + 1][row] = v.y;
            As[c4 * 4 + 2][row] = v.z;
            As[c4 * 4 + 3][row] = v.w;
        }
#pragma unroll
        for (int l = 0; l < 2; l++) {
            int fi = tid + l * 256;
            int kk = fi >> 5, c4 = fi & 31;
            float4 v = *(const float4*)(g_Wc + (size_t)(kt + kk) * 128 + c4 * 4);
            float4 a = make_float4(v.x, v.x, v.y, v.y);
            float4 b = make_float4(v.z, v.z, v.w, v.w);
            *(float4*)&Bsd[kk][c4 * 8]     = a;
            *(float4*)&Bsd[kk][c4 * 8 + 4] = b;
        }
        __syncthreads();

        const unsigned long long* A64 = (const unsigned long long*)&As[0][0];
        const unsigned long long* B64 = (const unsigned long long*)&Bsd[0][0];
#pragma unroll
        for (int kk = 0; kk < 16; kk++) {
            unsigned long long ap[4], bp[8];
#pragma unroll
            for (int q = 0; q < 4; q++) ap[q] = A64[kk * 64 + tm * 4 + q];
#pragma unroll
            for (int j = 0; j < 4; j++) {
                bp[j]     = B64[kk * 128 + j * 16 + tn];
                bp[j + 4] = B64[kk * 128 + 64 + j * 16 + tn];
            }
#pragma unroll
            for (int q = 0; q < 4; q++)
#pragma unroll
                for (int j = 0; j < 8; j++) acc[q][j] = ffma2(ap[q], bp[j], acc[q][j]);
        }
        __syncthreads();
    }

    float bz4[4], bh4[4], g4[4], b4[4];
#pragma unroll
    for (int j = 0; j < 4; j++) {
        int f = tn + 16 * j;
        bz4[j] = bz[f]; bh4[j] = bh[f]; g4[j] = lng[f]; b4[j] = lnb[f];
    }
#pragma unroll
    for (int q = 0; q < 4; q++) {
#pragma unroll
        for (int h = 0; h < 2; h++) {
            int m = m0 + tm * 8 + 2 * q + h;
            float v[4], s1 = 0.f, s2 = 0.f;
#pragma unroll
            for (int j = 0; j < 4; j++) {
                float2 pz = *(float2*)&acc[q][j];
                float2 pg = *(float2*)&acc[q][j + 4];
                float zp = (h ? pz.y : pz.x) + bz4[j];
                float gp = (h ? pg.y : pg.x) + bh4[j];
                float zs = __fdividef(1.0f, 1.0f + __expf(-zp));
                float th = 1.0f - __fdividef(2.0f, __expf(2.0f * gp) + 1.0f);
                float val = (1.0f - zs) * th;
                val = val > 0.f ? val : 0.f;
                v[j] = val; s1 += val; s2 += val * val;
            }
#pragma unroll
            for (int msk = 1; msk < 16; msk <<= 1) {
                s1 += __shfl_xor_sync(0xffffffffu, s1, msk);
                s2 += __shfl_xor_sync(0xffffffffu, s2, msk);
            }
            float mean = s1 * (1.0f / 64.0f);
            float var  = s2 * (1.0f / 64.0f) - mean * mean;
            float rstd = rsqrtf(var + 1e-5f);
#pragma unroll
            for (int j = 0; j < 4; j++) {
                g_hln[(size_t)m * 64 + tn + 16 * j] = (v[j] - mean) * rstd * g4[j] + b4[j];
            }
        }
    }
}

// ------------------------------- final linear -------------------------------
__global__ void k_outinit(const float* __restrict__ lb, float* __restrict__ out) {
    int t = threadIdx.x;
    if (t < BB * CC) out[t] = lb[t % CC];
}

__global__ void k_final(const float* __restrict__ lw, float* __restrict__ out) {
    __shared__ float ws[10][1024];
    __shared__ float psum[8][16][10];
    int tid = threadIdx.x;
    int i0 = blockIdx.x * 1024;
    for (int idx = tid; idx < 10 * 1024; idx += 256) {
        int c = idx >> 10, ii = idx & 1023;
        ws[c][ii] = lw[(size_t)c * FLAT + i0 + ii];
    }
    __syncthreads();
    int wp = tid >> 5, lane = tid & 31;
    for (int b = 0; b < BB; b++) {
        float a[10];
#pragma unroll
        for (int c = 0; c < 10; c++) a[c] = 0.f;
#pragma unroll
        for (int r = 0; r < 4; r++) {
            int ii = r * 256 + tid;
            float hv = g_hln[(size_t)b * FLAT + i0 + ii];
#pragma unroll
            for (int c = 0; c < 10; c++) a[c] += hv * ws[c][ii];
        }
#pragma unroll
        for (int c = 0; c < 10; c++) {
            float s = a[c];
#pragma unroll
            for (int msk = 16; msk >= 1; msk >>= 1)
                s += __shfl_xor_sync(0xffffffffu, s, msk);
            if (lane == 0) psum[wp][b][c] = s;
        }
    }
    __syncthreads();
    if (tid < 160) {
        int b = tid / 10, c = tid % 10;
        float s = 0.f;
#pragma unroll
        for (int w = 0; w < 8; w++) s += psum[w][b][c];
        atomicAdd(&out[b * 10 + c], s);
    }
}

// ------------------------------- launcher -------------------------------
extern "C" void kernel_launch(void* const* d_in, const int* in_sizes, int n_in,
                              void* d_out, int out_size) {
    const float* x   = (const float*)d_in[0];
    const int*   ei  = (const int*)  d_in[1];
    const float* Wz  = (const float*)d_in[2];
    const float* bz  = (const float*)d_in[3];
    // d_in[4] = W_r, d_in[5] = b_r -- provably unused (hidden state is zero)
    const float* Wh  = (const float*)d_in[6];
    const float* bh  = (const float*)d_in[7];
    const float* lng = (const float*)d_in[8];
    const float* lnb = (const float*)d_in[9];
    const float* lw  = (const float*)d_in[10];
    const float* lb  = (const float*)d_in[11];
    float* out = (float*)d_out;

    k_init<<<(NN + 255) / 256, 256>>>();
    k_deg<<<(EE + 255) / 256, 256>>>(ei);
    k_scan<<<1, 1024>>>();
    k_fill<<<(EE + 255) / 256, 256>>>(ei);
    k_wc<<<(9 * 64 * 128 + 255) / 256, 256>>>(Wz, Wh);
    k_copyx<<<(MM * 16) / 256, 256>>>((const float4*)x);
    for (int k = 1; k <= 4; k++)
        k_prop2<<<dim3(4, SS, 2), 1024>>>(k);
    k_gemm<<<MM / 128, 256>>>(bz, bh, lng, lnb);
    k_outinit<<<1, 256>>>(lb, out);
    k_final<<<FLAT / 1024, 256>>>(lw, out);
}

// round 7
// speedup vs baseline: 1.1283x; 1.1283x over previous
#include <cuda_runtime.h>
#include <cstdint>

#define NN   1000
#define FF   64
#define BB   16
#define TT   12
#define CC   10
#define EE   16000
#define SS   (BB*TT)          // 192 snapshots
#define MM   (SS*NN)          // 192000 rows
#define KDIM 576              // 9 * 64
#define FLAT (TT*NN*FF)       // 768000 per batch

// SMEM floats layout for k_prop3
#define PSM_BUF  0            // 1000 x 33 padded rows
#define PSM_NBR  33000        // 16000 ints
#define PSM_PTR  49000        // 1001 ints
#define PSM_TOT  50004
#define PSM_BYTES (PSM_TOT * 4)

// ------------------------- device scratch (static, allowed) -------------------------
__device__ int   g_deg_out[NN];
__device__ int   g_deg_in[NN];
__device__ int   g_ptr_out[NN + 1];
__device__ int   g_ptr_in[NN + 1];
__device__ int   g_cur_out[NN];
__device__ int   g_cur_in[NN];
__device__ int   g_nbr_out[EE];
__device__ int   g_nbr_in[EE];
__device__ float g_invdeg_in[NN];
__device__ float g_invdeg_out[NN];
__device__ float g_Wc[KDIM * 128];            // 576 x 128 combined weights
__device__ float g_basis[(size_t)MM * KDIM];  // 442 MB Chebyshev basis
__device__ float g_hln[(size_t)MM * FF];      // 49 MB post-LN hidden

// ------------------------------- helpers -------------------------------
__device__ __forceinline__ unsigned long long ffma2(unsigned long long a,
                                                    unsigned long long b,
                                                    unsigned long long c) {
    unsigned long long d;
    asm("fma.rn.f32x2 %0, %1, %2, %3;" : "=l"(d) : "l"(a), "l"(b), "l"(c));
    return d;
}

// ------------------------------- setup kernels -------------------------------
__global__ void k_init() {
    int i = blockIdx.x * blockDim.x + threadIdx.x;
    if (i < NN) { g_deg_out[i] = 0; g_deg_in[i] = 0; }
}

__global__ void k_deg(const int* __restrict__ ei) {
    int e = blockIdx.x * blockDim.x + threadIdx.x;
    if (e < EE) {
        atomicAdd(&g_deg_out[ei[e]], 1);       // row = src
        atomicAdd(&g_deg_in[ei[EE + e]], 1);   // col = dst
    }
}

__global__ void k_scan() {
    __shared__ int buf[1024];
    int t = threadIdx.x;
    int v = (t < NN) ? g_deg_in[t] : 0;
    buf[t] = v; __syncthreads();
    for (int off = 1; off < 1024; off <<= 1) {
        int a = buf[t];
        int b = (t >= off) ? buf[t - off] : 0;
        __syncthreads();
        buf[t] = a + b;
        __syncthreads();
    }
    if (t < NN) {
        int incl = buf[t];
        g_ptr_out[t] = incl - v;
        g_cur_out[t] = incl - v;
        g_invdeg_in[t] = (v > 0) ? 1.0f / (float)v : 0.0f;
        if (t == NN - 1) g_ptr_out[NN] = incl;
    }
    __syncthreads();
    int v2 = (t < NN) ? g_deg_out[t] : 0;
    buf[t] = v2; __syncthreads();
    for (int off = 1; off < 1024; off <<= 1) {
        int a = buf[t];
        int b = (t >= off) ? buf[t - off] : 0;
        __syncthreads();
        buf[t] = a + b;
        __syncthreads();
    }
    if (t < NN) {
        int incl = buf[t];
        g_ptr_in[t] = incl - v2;
        g_cur_in[t] = incl - v2;
        g_invdeg_out[t] = (v2 > 0) ? 1.0f / (float)v2 : 0.0f;
        if (t == NN - 1) g_ptr_in[NN] = incl;
    }
}

__global__ void k_fill(const int* __restrict__ ei) {
    int e = blockIdx.x * blockDim.x + threadIdx.x;
    if (e < EE) {
        int row = ei[e], col = ei[EE + e];
        int p = atomicAdd(&g_cur_out[col], 1);
        g_nbr_out[p] = row;
        int q = atomicAdd(&g_cur_in[row], 1);
        g_nbr_in[q] = col;
    }
}

// Combined weight Wc[j*64+i][c]: c<64 -> z (W_z), c>=64 -> h (W_h)
__global__ void k_wc(const float* __restrict__ Wz, const float* __restrict__ Wh) {
    int idx = blockIdx.x * blockDim.x + threadIdx.x;
    if (idx >= 9 * 64 * 128) return;
    int j = idx / 8192;
    int r = idx - j * 8192;
    int i = r >> 7;
    int c = r & 127;
    const float* W = (c < 64) ? Wz : Wh;
    int f = c & 63;
    float val;
    if (j == 0)       val = W[i * 64 + f] + W[5 * 8192 + i * 64 + f];
    else if (j <= 4)  val = W[(size_t)j * 8192 + i * 64 + f];
    else              val = W[(size_t)(5 + (j - 4)) * 8192 + i * 64 + f];
    g_Wc[(j * 64 + i) * 128 + c] = val;
}

__global__ void k_copyx(const float4* __restrict__ x4) {
    int idx = blockIdx.x * blockDim.x + threadIdx.x;
    if (idx >= MM * 16) return;
    int m = idx >> 4;
    int q = idx & 15;
    float4* dst = (float4*)g_basis;
    dst[(size_t)m * 144 + q] = x4[(size_t)m * 16 + q];
}

// ------------------------------- propagation: SMEM-source, warp-per-node -------------------------------
// CTA = (fhalf of 32 feats, snapshot, direction). 1024 threads = 32 warps.
// Stage: src values [1000 x 32] (out-dir pre-scaled by 1/deg_out[src]) + edge CSR
// into SMEM. Gather: warp per node, lane = feature, one 128-B conflict-free LDS
// per edge (bank = (node + lane) mod 32), uniform broadcast index load. Results
// go straight to global; buffer is read-only within the launch.
__global__ void __launch_bounds__(1024, 1)
k_prop3(int step) {
    extern __shared__ float sm[];
    float* buf   = sm + PSM_BUF;
    int*   s_nbr = (int*)(sm + PSM_NBR);
    int*   s_ptr = (int*)(sm + PSM_PTR);

    int fh  = blockIdx.x;            // 0..1
    int s   = blockIdx.y;            // 0..191
    int dir = blockIdx.z;            // 0 = out, 1 = in
    int tid = threadIdx.x;
    int w   = tid >> 5;              // warp 0..31
    int lane = tid & 31;

    int srcslot = (step == 1) ? 0 : ((dir ? 4 : 0) + step - 1);
    int dstslot = (dir ? 4 : 0) + step;
    float alpha = (step == 1) ? 1.0f : 2.0f;

    const int* gptr = dir ? g_ptr_in : g_ptr_out;
    const int* gnbr = dir ? g_nbr_in : g_nbr_out;

    size_t snap0 = (size_t)s * NN * KDIM;
    int fo = fh * 32;

    // ---- stage CSR ----
    for (int i = tid; i < EE; i += 1024) s_nbr[i] = gnbr[i];
    for (int i = tid; i <= NN; i += 1024) s_ptr[i] = gptr[i];
    // ---- stage source block (warp per node, lane = feature) ----
    for (int n = w; n < NN; n += 32) {
        float v = __ldg(g_basis + snap0 + (size_t)n * KDIM + srcslot * 64 + fo + lane);
        if (!dir) v *= __ldg(g_invdeg_out + n);    // pre-scale: edge weight = 1/deg_out[src]
        buf[n * 33 + lane] = v;
    }
    __syncthreads();

    // ---- gather phase ----
    for (int n = w; n < NN; n += 32) {
        int e0 = s_ptr[n], e1 = s_ptr[n + 1];
        float a0 = 0.f, a1 = 0.f;
        int e = e0;
        for (; e + 1 < e1; e += 2) {
            int v0 = s_nbr[e];
            int v1 = s_nbr[e + 1];
            a0 += buf[v0 * 33 + lane];
            a1 += buf[v1 * 33 + lane];
        }
        if (e < e1) a0 += buf[s_nbr[e] * 33 + lane];
        float res = a0 + a1;
        if (dir) res *= __ldg(g_invdeg_in + n);
        res *= alpha;
        size_t orow = snap0 + (size_t)n * KDIM;
        if (step >= 2)
            res -= __ldg(g_basis + orow + (size_t)(step - 2) * 64 + fo + lane);
        g_basis[orow + (size_t)dstslot * 64 + fo + lane] = res;
    }
}

// ------------------------------- fused GEMM + gate + LN (R1, proven) -------------------------------
__global__ void __launch_bounds__(256, 2)
k_gemm(const float* __restrict__ bz, const float* __restrict__ bh,
       const float* __restrict__ lng, const float* __restrict__ lnb) {
    __shared__ float As[16][128];     // A tile transposed: As[k][m]
    __shared__ float Bsd[16][256];    // B tile, dup-packed {b,b}

    int tid = threadIdx.x;
    int m0  = blockIdx.x * 128;
    int tm  = tid >> 4;
    int tn  = tid & 15;

    unsigned long long acc[4][8];
#pragma unroll
    for (int q = 0; q < 4; q++)
#pragma unroll
        for (int j = 0; j < 8; j++) acc[q][j] = 0ull;

    for (int kt = 0; kt < KDIM; kt += 16) {
#pragma unroll
        for (int l = 0; l < 2; l++) {
            int fi = tid + l * 256;
            int row = fi >> 2, c4 = fi & 3;
            float4 v = *(const float4*)(g_basis + (size_t)(m0 + row) * KDIM + kt + c4 * 4);
            As[c4 * 4 + 0][row] = v.x;
            As[c4 * 4 + 1][row] = v.y;
            As[c4 * 4 + 2][row] = v.z;
            As[c4 * 4 + 3][row] = v.w;
        }
#pragma unroll
        for (int l = 0; l < 2; l++) {
            int fi = tid + l * 256;
            int kk = fi >> 5, c4 = fi & 31;
            float4 v = *(const float4*)(g_Wc + (size_t)(kt + kk) * 128 + c4 * 4);
            float4 a = make_float4(v.x, v.x, v.y, v.y);
            float4 b = make_float4(v.z, v.z, v.w, v.w);
            *(float4*)&Bsd[kk][c4 * 8]     = a;
            *(float4*)&Bsd[kk][c4 * 8 + 4] = b;
        }
        __syncthreads();

        const unsigned long long* A64 = (const unsigned long long*)&As[0][0];
        const unsigned long long* B64 = (const unsigned long long*)&Bsd[0][0];
#pragma unroll
        for (int kk = 0; kk < 16; kk++) {
            unsigned long long ap[4], bp[8];
#pragma unroll
            for (int q = 0; q < 4; q++) ap[q] = A64[kk * 64 + tm * 4 + q];
#pragma unroll
            for (int j = 0; j < 4; j++) {
                bp[j]     = B64[kk * 128 + j * 16 + tn];
                bp[j + 4] = B64[kk * 128 + 64 + j * 16 + tn];
            }
#pragma unroll
            for (int q = 0; q < 4; q++)
#pragma unroll
                for (int j = 0; j < 8; j++) acc[q][j] = ffma2(ap[q], bp[j], acc[q][j]);
        }
        __syncthreads();
    }

    float bz4[4], bh4[4], g4[4], b4[4];
#pragma unroll
    for (int j = 0; j < 4; j++) {
        int f = tn + 16 * j;
        bz4[j] = bz[f]; bh4[j] = bh[f]; g4[j] = lng[f]; b4[j] = lnb[f];
    }
#pragma unroll
    for (int q = 0; q < 4; q++) {
#pragma unroll
        for (int h = 0; h < 2; h++) {
            int m = m0 + tm * 8 + 2 * q + h;
            float v[4], s1 = 0.f, s2 = 0.f;
#pragma unroll
            for (int j = 0; j < 4; j++) {
                float2 pz = *(float2*)&acc[q][j];
                float2 pg = *(float2*)&acc[q][j + 4];
                float zp = (h ? pz.y : pz.x) + bz4[j];
                float gp = (h ? pg.y : pg.x) + bh4[j];
                float zs = __fdividef(1.0f, 1.0f + __expf(-zp));
                float th = 1.0f - __fdividef(2.0f, __expf(2.0f * gp) + 1.0f);
                float val = (1.0f - zs) * th;
                val = val > 0.f ? val : 0.f;
                v[j] = val; s1 += val; s2 += val * val;
            }
#pragma unroll
            for (int msk = 1; msk < 16; msk <<= 1) {
                s1 += __shfl_xor_sync(0xffffffffu, s1, msk);
                s2 += __shfl_xor_sync(0xffffffffu, s2, msk);
            }
            float mean = s1 * (1.0f / 64.0f);
            float var  = s2 * (1.0f / 64.0f) - mean * mean;
            float rstd = rsqrtf(var + 1e-5f);
#pragma unroll
            for (int j = 0; j < 4; j++) {
                g_hln[(size_t)m * 64 + tn + 16 * j] = (v[j] - mean) * rstd * g4[j] + b4[j];
            }
        }
    }
}

// ------------------------------- final linear -------------------------------
__global__ void k_outinit(const float* __restrict__ lb, float* __restrict__ out) {
    int t = threadIdx.x;
    if (t < BB * CC) out[t] = lb[t % CC];
}

__global__ void k_final(const float* __restrict__ lw, float* __restrict__ out) {
    __shared__ float ws[10][1024];
    __shared__ float psum[8][16][10];
    int tid = threadIdx.x;
    int i0 = blockIdx.x * 1024;
    for (int idx = tid; idx < 10 * 1024; idx += 256) {
        int c = idx >> 10, ii = idx & 1023;
        ws[c][ii] = lw[(size_t)c * FLAT + i0 + ii];
    }
    __syncthreads();
    int wp = tid >> 5, lane = tid & 31;
    for (int b = 0; b < BB; b++) {
        float a[10];
#pragma unroll
        for (int c = 0; c < 10; c++) a[c] = 0.f;
#pragma unroll
        for (int r = 0; r < 4; r++) {
            int ii = r * 256 + tid;
            float hv = g_hln[(size_t)b * FLAT + i0 + ii];
#pragma unroll
            for (int c = 0; c < 10; c++) a[c] += hv * ws[c][ii];
        }
#pragma unroll
        for (int c = 0; c < 10; c++) {
            float s = a[c];
#pragma unroll
            for (int msk = 16; msk >= 1; msk >>= 1)
                s += __shfl_xor_sync(0xffffffffu, s, msk);
            if (lane == 0) psum[wp][b][c] = s;
        }
    }
    __syncthreads();
    if (tid < 160) {
        int b = tid / 10, c = tid % 10;
        float s = 0.f;
#pragma unroll
        for (int w = 0; w < 8; w++) s += psum[w][b][c];
        atomicAdd(&out[b * 10 + c], s);
    }
}

// ------------------------------- launcher -------------------------------
extern "C" void kernel_launch(void* const* d_in, const int* in_sizes, int n_in,
                              void* d_out, int out_size) {
    const float* x   = (const float*)d_in[0];
    const int*   ei  = (const int*)  d_in[1];
    const float* Wz  = (const float*)d_in[2];
    const float* bz  = (const float*)d_in[3];
    // d_in[4] = W_r, d_in[5] = b_r -- provably unused (hidden state is zero)
    const float* Wh  = (const float*)d_in[6];
    const float* bh  = (const float*)d_in[7];
    const float* lng = (const float*)d_in[8];
    const float* lnb = (const float*)d_in[9];
    const float* lw  = (const float*)d_in[10];
    const float* lb  = (const float*)d_in[11];
    float* out = (float*)d_out;

    cudaFuncSetAttribute(k_prop3, cudaFuncAttributeMaxDynamicSharedMemorySize, PSM_BYTES);

    k_init<<<(NN + 255) / 256, 256>>>();
    k_deg<<<(EE + 255) / 256, 256>>>(ei);
    k_scan<<<1, 1024>>>();
    k_fill<<<(EE + 255) / 256, 256>>>(ei);
    k_wc<<<(9 * 64 * 128 + 255) / 256, 256>>>(Wz, Wh);
    k_copyx<<<(MM * 16) / 256, 256>>>((const float4*)x);
    for (int k = 1; k <= 4; k++)
        k_prop3<<<dim3(2, SS, 2), 1024, PSM_BYTES>>>(k);
    k_gemm<<<MM / 128, 256>>>(bz, bh, lng, lnb);
    k_outinit<<<1, 256>>>(lb, out);
    k_final<<<FLAT / 1024, 256>>>(lw, out);
}